// round 14
// baseline (speedup 1.0000x reference)
#include <cuda_runtime.h>

#define NN 2048
#define FF 64
#define KK 8
#define GROUP 8
#define NGRP (NN / GROUP)     // 256 groups of 8
#define DENSEG 16             // dense phase: groups 0..15 = ranks 0..127
#define SPA (DENSEG * GROUP + 2 * GROUP)   // 144 staged pairs
#define NBUCK 4096
#define BSHIFT 20
#define BPT (NBUCK / 256)
#define FULLM 0xffffffffu

// Scratch: per-feature bucket-descending (x value, row byte-offset) pairs +
// exact per-group suffix-max stop bounds.
__device__ float2 g_sp[FF * NN];
__device__ float  g_bound[FF * NGRP];

__device__ __forceinline__ unsigned key_of(float v) {
    unsigned u = __float_as_uint(v);
    return (u & 0x80000000u) ? ~u : (u | 0x80000000u);
}
__device__ __forceinline__ float val_of(unsigned k) {
    unsigned u = (k & 0x80000000u) ? (k ^ 0x80000000u) : ~k;
    return __uint_as_float(u);
}

// One block per feature f: counting-sort rows into descending-bucket order,
// emit (x value, row byte-offset) + exact suffix-max bounds (shfl scans).
__global__ __launch_bounds__(256) void prep_kernel(const float* __restrict__ x) {
    const int tid = threadIdx.x;
    const int f = blockIdx.x;
    const unsigned lane = tid & 31, wrp = tid >> 5;
    const float NEG_INF = -__int_as_float(0x7f800000);

    __shared__ unsigned skey[NN];
    __shared__ int hist[NBUCK];
    __shared__ float sval[NN];
    __shared__ int wsum[8], wsufs[8];
    __shared__ float wmaxs[8], wsufm[8];
    __shared__ float inclmax[256];

    for (int i = tid; i < NBUCK; i += 256) hist[i] = 0;
    __syncthreads();

    // Pass 1: keys + histogram.
    for (int i = tid; i < NN; i += 256) {
        float v = x[(size_t)i * FF + f];
        unsigned k = key_of(v);
        skey[i] = k;
        atomicAdd(&hist[k >> BSHIFT], 1);
    }
    __syncthreads();

    // Pass 2: descending-exclusive bucket offsets via shfl suffix scan.
    const int base = tid * BPT;
    int csum = 0;
    #pragma unroll
    for (int j = 0; j < BPT; j++) csum += hist[base + j];
    int v = csum;
    #pragma unroll
    for (int d = 1; d < 32; d <<= 1) {
        int o = __shfl_down_sync(FULLM, v, d);
        if (lane + d < 32) v += o;
    }
    if (lane == 0) wsum[wrp] = v;
    __syncthreads();
    if (tid < 8) {
        int w = wsum[tid];
        #pragma unroll
        for (int d = 1; d < 8; d <<= 1) {
            int o = __shfl_down_sync(0xffu, w, d);
            if (tid + d < 8) w += o;
        }
        wsufs[tid] = w;
    }
    __syncthreads();
    int run = (v - csum) + ((wrp < 7) ? wsufs[wrp + 1] : 0);
    #pragma unroll
    for (int j = BPT - 1; j >= 0; j--) {
        int c = hist[base + j];
        hist[base + j] = run;
        run += c;
    }
    __syncthreads();

    // Pass 3: scatter (value, byte offset = idx * NN * 4).
    for (int i = tid; i < NN; i += 256) {
        unsigned k = skey[i];
        float vv = val_of(k);
        int pos = atomicAdd(&hist[k >> BSHIFT], 1);
        g_sp[f * NN + pos] = make_float2(vv, __int_as_float(i * (NN * 4)));
        sval[pos] = vv;
    }
    __syncthreads();

    // Pass 4: exact suffix-max bound per group of 8. After group g, all
    // remaining products <= max(suffix_max(g+1), 0): adj in [0,1).
    float gm = NEG_INF;
    #pragma unroll
    for (int j = 0; j < GROUP; j++) gm = fmaxf(gm, sval[tid * GROUP + j]);
    float vm = gm;
    #pragma unroll
    for (int d = 1; d < 32; d <<= 1) {
        float o = __shfl_down_sync(FULLM, vm, d);
        if (lane + d < 32) vm = fmaxf(vm, o);
    }
    if (lane == 0) wmaxs[wrp] = vm;
    __syncthreads();
    if (tid < 8) {
        float w = wmaxs[tid];
        #pragma unroll
        for (int d = 1; d < 8; d <<= 1) {
            float o = __shfl_down_sync(0xffu, w, d);
            if (tid + d < 8) w = fmaxf(w, o);
        }
        wsufm[tid] = w;
    }
    __syncthreads();
    inclmax[tid] = fmaxf(vm, (wrp < 7) ? wsufm[wrp + 1] : NEG_INF);
    __syncthreads();
    float b = (tid < 255) ? inclmax[tid + 1] : NEG_INF;
    g_bound[f * NGRP + tid] = fmaxf(b, 0.0f);
}

// blockIdx.y = f, blockIdx.x = m-tile. One thread per m.
// Dense branch-free scan of ranks 0..127 (P(not enough) ~ 1e-5), then a
// warp-cooperative repair pass for the rare straggler lanes: 32-wide chunks
// with exact count-based stop (#products >= bound reaches 8 => t8 >= bound),
// finished by a 5-stage bitonic butterfly merge of per-lane top-8s.
__global__ __launch_bounds__(256) void topk_kernel(const float* __restrict__ x,
                                                   const float* __restrict__ adj,
                                                   float* __restrict__ out) {
    __shared__ float2 s_p[SPA];
    const int f = blockIdx.y;
    const int tid = threadIdx.x;
    const int lane = tid & 31;
    const float NEG_INF = -__int_as_float(0x7f800000);

    if (tid < SPA) s_p[tid] = g_sp[f * NN + tid];
    __syncthreads();

    const float b15 = __ldg(&g_bound[f * NGRP + (DENSEG - 1)]);
    const int m = blockIdx.x * 256 + tid;
    const char* adjm = (const char*)(adj + m);

    float t[KK];
    #pragma unroll
    for (int j = 0; j < KK; j++) t[j] = NEG_INF;

    #define INSERT(tarr, cval)                                                \
        {   float c = (cval);                                                 \
            if (c > tarr[KK - 1]) {                                           \
                _Pragma("unroll")                                             \
                for (int j = 0; j < KK - 1; j++) {                            \
                    float w = fmaxf(tarr[j], c);                              \
                    c = fminf(tarr[j], c);                                    \
                    tarr[j] = w;                                              \
                }                                                             \
                tarr[KK - 1] = fmaxf(tarr[KK - 1], c);                        \
            }                                                                 \
        }
    #define LOADC(g, buf)                                                     \
        {   _Pragma("unroll")                                                 \
            for (int u = 0; u < GROUP; u++) {                                 \
                float2 p = s_p[(g) * GROUP + u];                              \
                buf[u] = __ldg((const float*)(adjm + __float_as_int(p.y)))    \
                         * p.x;                                               \
            }                                                                 \
        }
    #define CONSUME(buf)                                                      \
        {   _Pragma("unroll")                                                 \
            for (int u = 0; u < GROUP; u++) INSERT(t, buf[u]);                \
        }

    // ---- Dense phase: groups 0..15 (ranks 0..127), no branches/ballots. ----
    float ca[GROUP], cb[GROUP];
    LOADC(0, ca); LOADC(1, cb);
    #pragma unroll 1
    for (int g = 0; g < DENSEG; g += 2) {
        CONSUME(ca); LOADC(g + 2, ca);
        CONSUME(cb); LOADC(g + 3, cb);
    }

    // ---- Repair: warp-cooperative rescan for rare straggler lanes. ----
    unsigned strag = __ballot_sync(FULLM, !(t[KK - 1] >= b15));
    while (strag) {
        const int s = __ffs((int)strag) - 1;
        strag &= strag - 1;
        const int ms = __shfl_sync(FULLM, m, s);
        const char* adjs = (const char*)(adj + ms);

        float rt[KK];
        #pragma unroll
        for (int j = 0; j < KK; j++) rt[j] = NEG_INF;
        int cnt = 0;

        for (int c = 0; c < NN / 32; c++) {
            float2 p = __ldg(&g_sp[f * NN + c * 32 + lane]);
            float prod = __ldg((const float*)(adjs + __float_as_int(p.y)))
                         * p.x;
            INSERT(rt, prod);
            // Conservative count: earlier chunks counted vs >= bounds, which
            // are >= the current bound, so cnt never overcounts.
            float bnd = __ldg(&g_bound[f * NGRP + c * 4 + 3]);
            cnt += (prod >= bnd) ? 1 : 0;
            if (__reduce_add_sync(FULLM, cnt) >= KK) break;
        }

        // Butterfly merge of 32 sorted-desc 8-lists (all lanes end identical).
        #define CSWP(arr, i, jj)                                              \
            { float hi = fmaxf(arr[i], arr[jj]), lo = fminf(arr[i], arr[jj]); \
              arr[i] = hi; arr[jj] = lo; }
        #pragma unroll
        for (int d = 1; d < 32; d <<= 1) {
            float o[KK];
            #pragma unroll
            for (int j = 0; j < KK; j++)
                o[j] = __shfl_xor_sync(FULLM, rt[KK - 1 - j], d);
            #pragma unroll
            for (int j = 0; j < KK; j++) rt[j] = fmaxf(rt[j], o[j]);
            CSWP(rt, 0, 4); CSWP(rt, 1, 5); CSWP(rt, 2, 6); CSWP(rt, 3, 7);
            CSWP(rt, 0, 2); CSWP(rt, 1, 3); CSWP(rt, 4, 6); CSWP(rt, 5, 7);
            CSWP(rt, 0, 1); CSWP(rt, 2, 3); CSWP(rt, 4, 5); CSWP(rt, 6, 7);
        }
        #undef CSWP

        if (lane == s) {
            #pragma unroll
            for (int j = 0; j < KK; j++) t[j] = rt[j];
        }
    }

    // out[m][j][f]: j=0 is x[m][f], j=1..8 top values descending.
    size_t bse = (size_t)m * ((KK + 1) * FF) + f;
    out[bse] = x[(size_t)m * FF + f];
    #pragma unroll
    for (int j = 0; j < KK; j++) out[bse + (size_t)(j + 1) * FF] = t[j];

    #undef LOADC
    #undef INSERT
    #undef CONSUME
}

extern "C" void kernel_launch(void* const* d_in, const int* in_sizes, int n_in,
                              void* d_out, int out_size) {
    const float* x   = (const float*)d_in[0];
    const float* adj = (const float*)d_in[1];
    if (n_in >= 2 && in_sizes[0] > in_sizes[1]) {  // defensive: x is the smaller input
        const float* t = x; x = adj; adj = t;
    }
    float* out = (float*)d_out;

    prep_kernel<<<FF, 256>>>(x);
    topk_kernel<<<dim3(NN / 256, FF), 256>>>(x, adj, out);
}

// round 16
// speedup vs baseline: 1.0070x; 1.0070x over previous
#include <cuda_runtime.h>

#define NN 2048
#define FF 64
#define KK 8
#define GROUP 8
#define NGRP (NN / GROUP)     // 256 groups of 8
#define DENSEG 32             // dense phase: groups 0..31 = ranks 0..255
#define SPA (DENSEG * GROUP + 2 * GROUP)   // 272 staged pairs (incl. overrun)
#define NBUCK 4096
#define BSHIFT 20
#define BPT (NBUCK / 256)
#define FULLM 0xffffffffu

// Scratch: per-feature bucket-descending (x value, row byte-offset) pairs +
// exact per-group suffix-max stop bounds.
__device__ float2 g_sp[FF * NN];
__device__ float  g_bound[FF * NGRP];

__device__ __forceinline__ unsigned key_of(float v) {
    unsigned u = __float_as_uint(v);
    return (u & 0x80000000u) ? ~u : (u | 0x80000000u);
}
__device__ __forceinline__ float val_of(unsigned k) {
    unsigned u = (k & 0x80000000u) ? (k ^ 0x80000000u) : ~k;
    return __uint_as_float(u);
}

// One block per feature f: counting-sort rows into descending-bucket order,
// emit (x value, row byte-offset) + exact suffix-max bounds (shfl scans).
__global__ __launch_bounds__(256) void prep_kernel(const float* __restrict__ x) {
    const int tid = threadIdx.x;
    const int f = blockIdx.x;
    const unsigned lane = tid & 31, wrp = tid >> 5;
    const float NEG_INF = -__int_as_float(0x7f800000);

    __shared__ unsigned skey[NN];
    __shared__ int hist[NBUCK];
    __shared__ float sval[NN];
    __shared__ int wsum[8], wsufs[8];
    __shared__ float wmaxs[8], wsufm[8];
    __shared__ float inclmax[256];

    for (int i = tid; i < NBUCK; i += 256) hist[i] = 0;
    __syncthreads();

    // Pass 1: keys + histogram.
    for (int i = tid; i < NN; i += 256) {
        float v = x[(size_t)i * FF + f];
        unsigned k = key_of(v);
        skey[i] = k;
        atomicAdd(&hist[k >> BSHIFT], 1);
    }
    __syncthreads();

    // Pass 2: descending-exclusive bucket offsets via shfl suffix scan.
    const int base = tid * BPT;
    int csum = 0;
    #pragma unroll
    for (int j = 0; j < BPT; j++) csum += hist[base + j];
    int v = csum;
    #pragma unroll
    for (int d = 1; d < 32; d <<= 1) {
        int o = __shfl_down_sync(FULLM, v, d);
        if (lane + d < 32) v += o;
    }
    if (lane == 0) wsum[wrp] = v;
    __syncthreads();
    if (tid < 8) {
        int w = wsum[tid];
        #pragma unroll
        for (int d = 1; d < 8; d <<= 1) {
            int o = __shfl_down_sync(0xffu, w, d);
            if (tid + d < 8) w += o;
        }
        wsufs[tid] = w;
    }
    __syncthreads();
    int run = (v - csum) + ((wrp < 7) ? wsufs[wrp + 1] : 0);
    #pragma unroll
    for (int j = BPT - 1; j >= 0; j--) {
        int c = hist[base + j];
        hist[base + j] = run;
        run += c;
    }
    __syncthreads();

    // Pass 3: scatter (value, byte offset = idx * NN * 4).
    for (int i = tid; i < NN; i += 256) {
        unsigned k = skey[i];
        float vv = val_of(k);
        int pos = atomicAdd(&hist[k >> BSHIFT], 1);
        g_sp[f * NN + pos] = make_float2(vv, __int_as_float(i * (NN * 4)));
        sval[pos] = vv;
    }
    __syncthreads();

    // Pass 4: exact suffix-max bound per group of 8. After group g, all
    // remaining products <= max(suffix_max(g+1), 0): adj in [0,1).
    float gm = NEG_INF;
    #pragma unroll
    for (int j = 0; j < GROUP; j++) gm = fmaxf(gm, sval[tid * GROUP + j]);
    float vm = gm;
    #pragma unroll
    for (int d = 1; d < 32; d <<= 1) {
        float o = __shfl_down_sync(FULLM, vm, d);
        if (lane + d < 32) vm = fmaxf(vm, o);
    }
    if (lane == 0) wmaxs[wrp] = vm;
    __syncthreads();
    if (tid < 8) {
        float w = wmaxs[tid];
        #pragma unroll
        for (int d = 1; d < 8; d <<= 1) {
            float o = __shfl_down_sync(0xffu, w, d);
            if (tid + d < 8) w = fmaxf(w, o);
        }
        wsufm[tid] = w;
    }
    __syncthreads();
    inclmax[tid] = fmaxf(vm, (wrp < 7) ? wsufm[wrp + 1] : NEG_INF);
    __syncthreads();
    float b = (tid < 255) ? inclmax[tid + 1] : NEG_INF;
    g_bound[f * NGRP + tid] = fmaxf(b, 0.0f);
}

// blockIdx.y = f, blockIdx.x = m-tile. One thread per m.
// Dense branch-free scan of ranks 0..255. Stop test against the exact bound
// b_255 = max(x_(256..), 0): P(t7 < b) ~ Poisson(~50 qualifying products in
// the prefix, need 8) ~ 1e-15 -> repair is a correctness safety net that
// statistically never executes.
__global__ __launch_bounds__(256) void topk_kernel(const float* __restrict__ x,
                                                   const float* __restrict__ adj,
                                                   float* __restrict__ out) {
    __shared__ float2 s_p[SPA];
    const int f = blockIdx.y;
    const int tid = threadIdx.x;
    const int lane = tid & 31;
    const float NEG_INF = -__int_as_float(0x7f800000);

    // R15 bug: `if (tid < SPA)` left entries 256..271 uninitialized and the
    // pipeline-overrun LOADC read garbage offsets -> misaligned address.
    for (int i = tid; i < SPA; i += 256) s_p[i] = g_sp[f * NN + i];
    __syncthreads();

    const float bden = __ldg(&g_bound[f * NGRP + (DENSEG - 1)]);
    const int m = blockIdx.x * 256 + tid;
    const char* adjm = (const char*)(adj + m);

    float t[KK];
    #pragma unroll
    for (int j = 0; j < KK; j++) t[j] = NEG_INF;

    #define INSERT(tarr, cval)                                                \
        {   float c = (cval);                                                 \
            if (c > tarr[KK - 1]) {                                           \
                _Pragma("unroll")                                             \
                for (int j = 0; j < KK - 1; j++) {                            \
                    float w = fmaxf(tarr[j], c);                              \
                    c = fminf(tarr[j], c);                                    \
                    tarr[j] = w;                                              \
                }                                                             \
                tarr[KK - 1] = fmaxf(tarr[KK - 1], c);                        \
            }                                                                 \
        }
    #define LOADC(g, buf)                                                     \
        {   _Pragma("unroll")                                                 \
            for (int u = 0; u < GROUP; u++) {                                 \
                float2 p = s_p[(g) * GROUP + u];                              \
                buf[u] = __ldg((const float*)(adjm + __float_as_int(p.y)))    \
                         * p.x;                                               \
            }                                                                 \
        }
    #define CONSUME(buf)                                                      \
        {   _Pragma("unroll")                                                 \
            for (int u = 0; u < GROUP; u++) INSERT(t, buf[u]);                \
        }

    // ---- Dense phase: groups 0..31 (ranks 0..255), no branches/ballots. ----
    float ca[GROUP], cb[GROUP];
    LOADC(0, ca); LOADC(1, cb);
    #pragma unroll 1
    for (int g = 0; g < DENSEG; g += 2) {
        CONSUME(ca); LOADC(g + 2, ca);
        CONSUME(cb); LOADC(g + 3, cb);
    }

    // ---- Repair: warp-cooperative rescan, statistically never taken. ----
    unsigned strag = __ballot_sync(FULLM, !(t[KK - 1] >= bden));
    while (strag) {
        const int s = __ffs((int)strag) - 1;
        strag &= strag - 1;
        const int ms = __shfl_sync(FULLM, m, s);
        const char* adjs = (const char*)(adj + ms);

        float rt[KK];
        #pragma unroll
        for (int j = 0; j < KK; j++) rt[j] = NEG_INF;
        int cnt = 0;

        for (int c = 0; c < NN / 32; c++) {
            float2 p = __ldg(&g_sp[f * NN + c * 32 + lane]);
            float prod = __ldg((const float*)(adjs + __float_as_int(p.y)))
                         * p.x;
            INSERT(rt, prod);
            // Conservative count: earlier chunks counted vs >= bounds, so cnt
            // never overcounts qualifying products.
            float bnd = __ldg(&g_bound[f * NGRP + c * 4 + 3]);
            cnt += (prod >= bnd) ? 1 : 0;
            if (__reduce_add_sync(FULLM, cnt) >= KK) break;
        }

        // Butterfly merge of 32 sorted-desc 8-lists (all lanes end identical).
        #define CSWP(arr, i, jj)                                              \
            { float hi = fmaxf(arr[i], arr[jj]), lo = fminf(arr[i], arr[jj]); \
              arr[i] = hi; arr[jj] = lo; }
        #pragma unroll
        for (int d = 1; d < 32; d <<= 1) {
            float o[KK];
            #pragma unroll
            for (int j = 0; j < KK; j++)
                o[j] = __shfl_xor_sync(FULLM, rt[KK - 1 - j], d);
            #pragma unroll
            for (int j = 0; j < KK; j++) rt[j] = fmaxf(rt[j], o[j]);
            CSWP(rt, 0, 4); CSWP(rt, 1, 5); CSWP(rt, 2, 6); CSWP(rt, 3, 7);
            CSWP(rt, 0, 2); CSWP(rt, 1, 3); CSWP(rt, 4, 6); CSWP(rt, 5, 7);
            CSWP(rt, 0, 1); CSWP(rt, 2, 3); CSWP(rt, 4, 5); CSWP(rt, 6, 7);
        }
        #undef CSWP

        if (lane == s) {
            #pragma unroll
            for (int j = 0; j < KK; j++) t[j] = rt[j];
        }
    }

    // out[m][j][f]: j=0 is x[m][f], j=1..8 top values descending.
    size_t bse = (size_t)m * ((KK + 1) * FF) + f;
    out[bse] = x[(size_t)m * FF + f];
    #pragma unroll
    for (int j = 0; j < KK; j++) out[bse + (size_t)(j + 1) * FF] = t[j];

    #undef LOADC
    #undef INSERT
    #undef CONSUME
}

extern "C" void kernel_launch(void* const* d_in, const int* in_sizes, int n_in,
                              void* d_out, int out_size) {
    const float* x   = (const float*)d_in[0];
    const float* adj = (const float*)d_in[1];
    if (n_in >= 2 && in_sizes[0] > in_sizes[1]) {  // defensive: x is the smaller input
        const float* t = x; x = adj; adj = t;
    }
    float* out = (float*)d_out;

    prep_kernel<<<FF, 256>>>(x);
    topk_kernel<<<dim3(NN / 256, FF), 256>>>(x, adj, out);
}